// round 1
// baseline (speedup 1.0000x reference)
#include <cuda_runtime.h>
#include <math.h>

#define BB   8
#define NN   2048
#define FIN  512
#define FOUT 256

// Intermediates (device globals: no allocation allowed in kernel_launch)
__device__ float g_h[(size_t)BB * NN * FOUT];   // 16.8 MB
__device__ float g_f[BB * NN];
__device__ float g_g[BB * NN];

typedef unsigned long long ull;

__device__ __forceinline__ void fma2(ull &acc, ull a, ull b) {
    asm("fma.rn.f32x2 %0, %1, %2, %0;" : "+l"(acc) : "l"(a), "l"(b));
}
__device__ __forceinline__ float2 unpack2(ull v) {
    float2 r; asm("mov.b64 {%0, %1}, %2;" : "=f"(r.x), "=f"(r.y) : "l"(v)); return r;
}

// ---------------------------------------------------------------------------
// Kernel 1: h = x @ W  (M=16384, K=512, N=256), fused f = h@a1, g = h@a2.
// 128 blocks x 256 threads. Block computes 128 rows x all 256 cols.
// smem: xdup [32][260] (duplicated pairs), ws [32][256].
// ---------------------------------------------------------------------------
__global__ __launch_bounds__(256, 1)
void gemm_h_kernel(const float* __restrict__ x, const float* __restrict__ W,
                   const float* __restrict__ a)
{
    extern __shared__ float sm[];
    float* xdup = sm;          // 32 * 260 = 8320 floats
    float* ws   = sm + 8320;   // 32 * 256 = 8192 floats

    const int t    = threadIdx.x;
    const int m0   = blockIdx.x * 128;
    const int ti   = t >> 4;      // 0..15 (i-group: 8 rows each)
    const int to   = t & 15;      // 0..15 (o-group: 16 cols each)
    const int ii   = t & 127;     // row owned for x staging
    const int half = t >> 7;      // 0/1 (k-half of 16)

    ull acc[8][8];
    #pragma unroll
    for (int s = 0; s < 8; s++)
        #pragma unroll
        for (int q = 0; q < 8; q++) acc[s][q] = 0ull;

    const float* xr = x + (size_t)(m0 + ii) * FIN + half * 16;
    const int wkk = t >> 3;        // 0..31
    const int wo  = (t & 7) * 4;   // 0,4,...,28

    for (int k0 = 0; k0 < FIN; k0 += 32) {
        __syncthreads();
        // stage x tile, duplicated pairs: xdup[kk][2*ii] = xdup[kk][2*ii+1] = x
        #pragma unroll
        for (int q = 0; q < 4; q++) {
            float4 v = *(const float4*)(xr + k0 + 4 * q);
            int kk = half * 16 + 4 * q;
            *(float2*)(xdup + (kk + 0) * 260 + 2 * ii) = make_float2(v.x, v.x);
            *(float2*)(xdup + (kk + 1) * 260 + 2 * ii) = make_float2(v.y, v.y);
            *(float2*)(xdup + (kk + 2) * 260 + 2 * ii) = make_float2(v.z, v.z);
            *(float2*)(xdup + (kk + 3) * 260 + 2 * ii) = make_float2(v.w, v.w);
        }
        // stage W tile
        const float* wr = W + (size_t)(k0 + wkk) * FOUT + wo;
        #pragma unroll
        for (int m = 0; m < 8; m++)
            *(float4*)(ws + wkk * 256 + wo + 32 * m) = *(const float4*)(wr + 32 * m);
        __syncthreads();

        #pragma unroll 2
        for (int kk = 0; kk < 32; kk++) {
            const float* prow = xdup + kk * 260 + 16 * ti;
            const float* hrow = ws   + kk * 256 + 16 * to;
            ulonglong2 pA = *(const ulonglong2*)(prow);
            ulonglong2 pB = *(const ulonglong2*)(prow + 4);
            ulonglong2 pC = *(const ulonglong2*)(prow + 8);
            ulonglong2 pD = *(const ulonglong2*)(prow + 12);
            ulonglong2 hA = *(const ulonglong2*)(hrow);
            ulonglong2 hB = *(const ulonglong2*)(hrow + 4);
            ulonglong2 hC = *(const ulonglong2*)(hrow + 8);
            ulonglong2 hD = *(const ulonglong2*)(hrow + 12);
            ull P[8] = {pA.x, pA.y, pB.x, pB.y, pC.x, pC.y, pD.x, pD.y};
            ull H[8] = {hA.x, hA.y, hB.x, hB.y, hC.x, hC.y, hD.x, hD.y};
            #pragma unroll
            for (int s = 0; s < 8; s++)
                #pragma unroll
                for (int q = 0; q < 8; q++) fma2(acc[s][q], P[s], H[q]);
        }
    }

    // epilogue: write h, fused f/g = h @ a1/a2
    float a1v[16], a2v[16];
    #pragma unroll
    for (int m = 0; m < 16; m++) {
        a1v[m] = __ldg(a + to * 16 + m);
        a2v[m] = __ldg(a + FOUT + to * 16 + m);
    }
    #pragma unroll
    for (int s = 0; s < 8; s++) {
        int row = m0 + ti * 8 + s;
        float* hr = g_h + (size_t)row * FOUT + to * 16;
        float fp = 0.f, gp = 0.f;
        #pragma unroll
        for (int q2 = 0; q2 < 4; q2++) {
            float2 va = unpack2(acc[s][2 * q2]);
            float2 vb = unpack2(acc[s][2 * q2 + 1]);
            fp += va.x * a1v[4*q2] + va.y * a1v[4*q2+1] + vb.x * a1v[4*q2+2] + vb.y * a1v[4*q2+3];
            gp += va.x * a2v[4*q2] + va.y * a2v[4*q2+1] + vb.x * a2v[4*q2+2] + vb.y * a2v[4*q2+3];
            float4 st = make_float4(va.x, va.y, vb.x, vb.y);
            *(float4*)(hr + 4 * q2) = st;
        }
        // reduce across the 16 lanes sharing this row (width-16 segments)
        #pragma unroll
        for (int d = 8; d >= 1; d >>= 1) {
            fp += __shfl_down_sync(0xffffffffu, fp, d, 16);
            gp += __shfl_down_sync(0xffffffffu, gp, d, 16);
        }
        if (to == 0) { g_f[row] = fp; g_g[row] = gp; }
    }
}

// ---------------------------------------------------------------------------
// Kernel 2: fused masked-softmax attention + P@H + elu (single pass,
// unnormalized softmax; adj read exactly once).
// 128 blocks x 256 threads; block = (batch b, 128-row i-tile), Jt=32.
// smem: p2 [32][260] duplicated p-pairs, hs [32][256], gs[2048], fs[128],
//       dsum[2][128].
// ---------------------------------------------------------------------------
__global__ __launch_bounds__(256, 1)
void attn_kernel(const int* __restrict__ adj, float* __restrict__ out)
{
    extern __shared__ float sm[];
    float* p2   = sm;                    // 8320 floats
    float* hs   = sm + 8320;             // 8192 floats
    float* gs   = hs + 8192;             // 2048
    float* fs   = gs + 2048;             // 128
    float* dsum = fs + 128;              // 256

    const int t    = threadIdx.x;
    const int b    = blockIdx.x >> 4;
    const int i0   = (blockIdx.x & 15) << 7;
    const int ti   = t >> 4;
    const int to   = t & 15;
    const int ii   = t & 127;
    const int half = t >> 7;

    for (int j = t; j < NN; j += 256) gs[j] = g_g[b * NN + j];
    if (t < 128) fs[t] = g_f[b * NN + i0 + t];

    ull acc[8][8];
    #pragma unroll
    for (int s = 0; s < 8; s++)
        #pragma unroll
        for (int q = 0; q < 8; q++) acc[s][q] = 0ull;
    float dloc = 0.f;

    __syncthreads();
    const float fv = fs[ii];
    const int*   adjrow = adj + ((size_t)b * NN + i0 + ii) * NN + half * 16;
    const float* hb     = g_h + (size_t)b * NN * FOUT;
    const int hjr = t >> 3;          // 0..31 row for h staging
    const int hoc = (t & 7) * 4;     // col base

    for (int jt = 0; jt < NN; jt += 32) {
        __syncthreads();
        // p-tile: p = adj>0 ? exp(lrelu(f_i + g_j)) : 0  (stored duplicated)
        #pragma unroll
        for (int q = 0; q < 4; q++) {
            int4 av = *(const int4*)(adjrow + jt + 4 * q);
            int jjb = half * 16 + 4 * q;
            float z0 = fv + gs[jt + jjb + 0]; z0 = z0 >= 0.f ? z0 : 0.2f * z0;
            float z1 = fv + gs[jt + jjb + 1]; z1 = z1 >= 0.f ? z1 : 0.2f * z1;
            float z2 = fv + gs[jt + jjb + 2]; z2 = z2 >= 0.f ? z2 : 0.2f * z2;
            float z3 = fv + gs[jt + jjb + 3]; z3 = z3 >= 0.f ? z3 : 0.2f * z3;
            float p0 = (av.x > 0) ? __expf(z0) : 0.f;
            float p1 = (av.y > 0) ? __expf(z1) : 0.f;
            float pp2 = (av.z > 0) ? __expf(z2) : 0.f;
            float p3 = (av.w > 0) ? __expf(z3) : 0.f;
            dloc += p0 + p1 + pp2 + p3;
            *(float2*)(p2 + (jjb + 0) * 260 + 2 * ii) = make_float2(p0, p0);
            *(float2*)(p2 + (jjb + 1) * 260 + 2 * ii) = make_float2(p1, p1);
            *(float2*)(p2 + (jjb + 2) * 260 + 2 * ii) = make_float2(pp2, pp2);
            *(float2*)(p2 + (jjb + 3) * 260 + 2 * ii) = make_float2(p3, p3);
        }
        // h-tile stage
        const float* hrowg = hb + (size_t)(jt + hjr) * FOUT + hoc;
        #pragma unroll
        for (int m = 0; m < 8; m++)
            *(float4*)(hs + hjr * 256 + hoc + 32 * m) = *(const float4*)(hrowg + 32 * m);
        __syncthreads();

        // GEMM: acc[i][o] += p[i][j] * h[j][o]
        #pragma unroll 2
        for (int jj = 0; jj < 32; jj++) {
            const float* prow = p2 + jj * 260 + 16 * ti;
            const float* hrow = hs + jj * 256 + 16 * to;
            ulonglong2 pA = *(const ulonglong2*)(prow);
            ulonglong2 pB = *(const ulonglong2*)(prow + 4);
            ulonglong2 pC = *(const ulonglong2*)(prow + 8);
            ulonglong2 pD = *(const ulonglong2*)(prow + 12);
            ulonglong2 hA = *(const ulonglong2*)(hrow);
            ulonglong2 hB = *(const ulonglong2*)(hrow + 4);
            ulonglong2 hC = *(const ulonglong2*)(hrow + 8);
            ulonglong2 hD = *(const ulonglong2*)(hrow + 12);
            ull P[8] = {pA.x, pA.y, pB.x, pB.y, pC.x, pC.y, pD.x, pD.y};
            ull H[8] = {hA.x, hA.y, hB.x, hB.y, hC.x, hC.y, hD.x, hD.y};
            #pragma unroll
            for (int s = 0; s < 8; s++)
                #pragma unroll
                for (int q = 0; q < 8; q++) fma2(acc[s][q], P[s], H[q]);
        }
    }

    // denominators
    dsum[half * 128 + ii] = dloc;
    __syncthreads();

    #pragma unroll
    for (int s = 0; s < 8; s++) {
        int ir = ti * 8 + s;
        float den = dsum[ir] + dsum[128 + ir];
        float inv = (den > 0.f) ? (1.f / den) : 0.f;
        float* orow = out + ((size_t)b * NN + i0 + ir) * FOUT + to * 16;
        #pragma unroll
        for (int q2 = 0; q2 < 4; q2++) {
            float2 va = unpack2(acc[s][2 * q2]);
            float2 vb = unpack2(acc[s][2 * q2 + 1]);
            float r0 = va.x * inv, r1 = va.y * inv, r2 = vb.x * inv, r3 = vb.y * inv;
            r0 = r0 > 0.f ? r0 : expm1f(r0);
            r1 = r1 > 0.f ? r1 : expm1f(r1);
            r2 = r2 > 0.f ? r2 : expm1f(r2);
            r3 = r3 > 0.f ? r3 : expm1f(r3);
            *(float4*)(orow + 4 * q2) = make_float4(r0, r1, r2, r3);
        }
    }
}

// ---------------------------------------------------------------------------
extern "C" void kernel_launch(void* const* d_in, const int* in_sizes, int n_in,
                              void* d_out, int out_size)
{
    const float* x   = (const float*)d_in[0];
    const int*   adj = (const int*)d_in[1];
    const float* W   = (const float*)d_in[2];
    const float* a   = (const float*)d_in[3];
    float*       out = (float*)d_out;

    const int smem1 = (8320 + 8192) * 4;                       // 66048 B
    const int smem2 = (8320 + 8192 + 2048 + 128 + 256) * 4;    // 75776 B
    cudaFuncSetAttribute(gemm_h_kernel, cudaFuncAttributeMaxDynamicSharedMemorySize, smem1);
    cudaFuncSetAttribute(attn_kernel,   cudaFuncAttributeMaxDynamicSharedMemorySize, smem2);

    gemm_h_kernel<<<128, 256, smem1>>>(x, W, a);
    attn_kernel<<<128, 256, smem2>>>(adj, out);
}

// round 3
// speedup vs baseline: 2.3109x; 2.3109x over previous
#include <cuda_runtime.h>
#include <math.h>
#include <stdint.h>

#define BB   8
#define NN   2048
#define FIN  512
#define FOUT 256

__device__ float g_h[(size_t)BB * NN * FOUT];   // 16.8 MB
__device__ float g_f[BB * NN];
__device__ float g_g[BB * NN];

typedef unsigned long long ull;

__device__ __forceinline__ void fma2(ull &acc, ull a, ull b) {
    asm("fma.rn.f32x2 %0, %1, %2, %0;" : "+l"(acc) : "l"(a), "l"(b));
}
__device__ __forceinline__ float2 unpack2(ull v) {
    float2 r; asm("mov.b64 {%0, %1}, %2;" : "=f"(r.x), "=f"(r.y) : "l"(v)); return r;
}
__device__ __forceinline__ uint32_t to_tf32(float f) {
    uint32_t r; asm("cvt.rna.tf32.f32 %0, %1;" : "=r"(r) : "f"(f)); return r;
}
__device__ __forceinline__ void mma_tf32(float* d, const uint32_t* a, const uint32_t* b) {
    asm volatile(
        "mma.sync.aligned.m16n8k8.row.col.f32.tf32.tf32.f32 "
        "{%0,%1,%2,%3}, {%4,%5,%6,%7}, {%8,%9}, {%0,%1,%2,%3};"
        : "+f"(d[0]), "+f"(d[1]), "+f"(d[2]), "+f"(d[3])
        : "r"(a[0]), "r"(a[1]), "r"(a[2]), "r"(a[3]), "r"(b[0]), "r"(b[1]));
}

// ---------------------------------------------------------------------------
// Kernel 1: h = x @ W (fp32 f32x2), fused f = h@a1, g = h@a2.  (R1, proven)
// ---------------------------------------------------------------------------
__global__ __launch_bounds__(256, 1)
void gemm_h_kernel(const float* __restrict__ x, const float* __restrict__ W,
                   const float* __restrict__ a)
{
    extern __shared__ float sm[];
    float* xdup = sm;
    float* ws   = sm + 8320;

    const int t    = threadIdx.x;
    const int m0   = blockIdx.x * 128;
    const int ti   = t >> 4;
    const int to   = t & 15;
    const int ii   = t & 127;
    const int half = t >> 7;

    ull acc[8][8];
    #pragma unroll
    for (int s = 0; s < 8; s++)
        #pragma unroll
        for (int q = 0; q < 8; q++) acc[s][q] = 0ull;

    const float* xr = x + (size_t)(m0 + ii) * FIN + half * 16;
    const int wkk = t >> 3;
    const int wo  = (t & 7) * 4;

    for (int k0 = 0; k0 < FIN; k0 += 32) {
        __syncthreads();
        #pragma unroll
        for (int q = 0; q < 4; q++) {
            float4 v = *(const float4*)(xr + k0 + 4 * q);
            int kk = half * 16 + 4 * q;
            *(float2*)(xdup + (kk + 0) * 260 + 2 * ii) = make_float2(v.x, v.x);
            *(float2*)(xdup + (kk + 1) * 260 + 2 * ii) = make_float2(v.y, v.y);
            *(float2*)(xdup + (kk + 2) * 260 + 2 * ii) = make_float2(v.z, v.z);
            *(float2*)(xdup + (kk + 3) * 260 + 2 * ii) = make_float2(v.w, v.w);
        }
        const float* wr = W + (size_t)(k0 + wkk) * FOUT + wo;
        #pragma unroll
        for (int m = 0; m < 8; m++)
            *(float4*)(ws + wkk * 256 + wo + 32 * m) = *(const float4*)(wr + 32 * m);
        __syncthreads();

        #pragma unroll 2
        for (int kk = 0; kk < 32; kk++) {
            const float* prow = xdup + kk * 260 + 16 * ti;
            const float* hrow = ws   + kk * 256 + 16 * to;
            ulonglong2 pA = *(const ulonglong2*)(prow);
            ulonglong2 pB = *(const ulonglong2*)(prow + 4);
            ulonglong2 pC = *(const ulonglong2*)(prow + 8);
            ulonglong2 pD = *(const ulonglong2*)(prow + 12);
            ulonglong2 hA = *(const ulonglong2*)(hrow);
            ulonglong2 hB = *(const ulonglong2*)(hrow + 4);
            ulonglong2 hC = *(const ulonglong2*)(hrow + 8);
            ulonglong2 hD = *(const ulonglong2*)(hrow + 12);
            ull P[8] = {pA.x, pA.y, pB.x, pB.y, pC.x, pC.y, pD.x, pD.y};
            ull H[8] = {hA.x, hA.y, hB.x, hB.y, hC.x, hC.y, hD.x, hD.y};
            #pragma unroll
            for (int s = 0; s < 8; s++)
                #pragma unroll
                for (int q = 0; q < 8; q++) fma2(acc[s][q], P[s], H[q]);
        }
    }

    float a1v[16], a2v[16];
    #pragma unroll
    for (int m = 0; m < 16; m++) {
        a1v[m] = __ldg(a + to * 16 + m);
        a2v[m] = __ldg(a + FOUT + to * 16 + m);
    }
    #pragma unroll
    for (int s = 0; s < 8; s++) {
        int row = m0 + ti * 8 + s;
        float* hr = g_h + (size_t)row * FOUT + to * 16;
        float fp = 0.f, gp = 0.f;
        #pragma unroll
        for (int q2 = 0; q2 < 4; q2++) {
            float2 va = unpack2(acc[s][2 * q2]);
            float2 vb = unpack2(acc[s][2 * q2 + 1]);
            fp += va.x * a1v[4*q2] + va.y * a1v[4*q2+1] + vb.x * a1v[4*q2+2] + vb.y * a1v[4*q2+3];
            gp += va.x * a2v[4*q2] + va.y * a2v[4*q2+1] + vb.x * a2v[4*q2+2] + vb.y * a2v[4*q2+3];
            *(float4*)(hr + 4 * q2) = make_float4(va.x, va.y, vb.x, vb.y);
        }
        #pragma unroll
        for (int d = 8; d >= 1; d >>= 1) {
            fp += __shfl_down_sync(0xffffffffu, fp, d, 16);
            gp += __shfl_down_sync(0xffffffffu, gp, d, 16);
        }
        if (to == 0) { g_f[row] = fp; g_g[row] = gp; }
    }
}

// ---------------------------------------------------------------------------
// Kernel 2: attention via mma.sync tf32 (m16n8k8), double-buffered smem.
// Block = (b, 128-row i-tile). Warp grid 2(i) x 4(o): warp = 64i x 64o.
// smem floats: dsum[256] | gs[2048] | ps[2][128*36] | hs[2][32*260]
// ---------------------------------------------------------------------------
#define SM_DSUM 0
#define SM_GS   256
#define SM_PS0  2304
#define SM_PS1  6912
#define SM_HS0  11520
#define SM_HS1  19840
#define PS_STRIDE 36
#define HS_STRIDE 260
#define ATTN_SMEM_FLOATS 28160

__global__ __launch_bounds__(256, 1)
void attn_kernel(const int* __restrict__ adj, float* __restrict__ out)
{
    extern __shared__ float smf[];

    const int t    = threadIdx.x;
    const int b    = blockIdx.x >> 4;
    const int i0   = (blockIdx.x & 15) << 7;
    const int warp = t >> 5;
    const int lane = t & 31;
    const int g    = lane >> 2;     // 0..7
    const int tig  = lane & 3;      // 0..3
    const int wi   = warp >> 2;     // 0..1 (i half)
    const int wo   = warp & 3;      // 0..3 (o quarter)

    // producer roles
    const int irow = t >> 1;        // 0..127 (p row)
    const int jh   = t & 1;         // j half (16 each)
    const int hjr  = t >> 3;        // 0..31  (h row)
    const int hoc  = (t & 7) * 4;   // h col base

    for (int j = t; j < NN; j += 256) smf[SM_GS + j] = g_g[b * NN + j];
    const float fv = g_f[b * NN + i0 + irow];
    const int*   adjrow = adj + ((size_t)b * NN + i0 + irow) * NN + jh * 16;
    const float* hb     = g_h + (size_t)b * NN * FOUT;

    float acc[4][8][4];
    #pragma unroll
    for (int ma = 0; ma < 4; ma++)
        #pragma unroll
        for (int na = 0; na < 8; na++)
            #pragma unroll
            for (int c = 0; c < 4; c++) acc[ma][na][c] = 0.f;
    float dloc = 0.f;
    __syncthreads();   // gs visible before first produce

    // ---- produce tile jtp into buffer jtp&1 ----
    auto produce = [&](int jtp) {
        float* ps = smf + (jtp & 1 ? SM_PS1 : SM_PS0);
        float* hs = smf + (jtp & 1 ? SM_HS1 : SM_HS0);
        const float* gsr = smf + SM_GS + jtp * 32 + jh * 16;
        #pragma unroll
        for (int q = 0; q < 4; q++) {
            int4 av = *(const int4*)(adjrow + jtp * 32 + 4 * q);
            float z0 = fv + gsr[4*q+0]; z0 = z0 >= 0.f ? z0 : 0.2f * z0;
            float z1 = fv + gsr[4*q+1]; z1 = z1 >= 0.f ? z1 : 0.2f * z1;
            float z2 = fv + gsr[4*q+2]; z2 = z2 >= 0.f ? z2 : 0.2f * z2;
            float z3 = fv + gsr[4*q+3]; z3 = z3 >= 0.f ? z3 : 0.2f * z3;
            float p0 = (av.x > 0) ? __expf(z0) : 0.f;
            float p1 = (av.y > 0) ? __expf(z1) : 0.f;
            float p2 = (av.z > 0) ? __expf(z2) : 0.f;
            float p3 = (av.w > 0) ? __expf(z3) : 0.f;
            dloc += p0 + p1 + p2 + p3;
            float4 st = make_float4(__uint_as_float(to_tf32(p0)),
                                    __uint_as_float(to_tf32(p1)),
                                    __uint_as_float(to_tf32(p2)),
                                    __uint_as_float(to_tf32(p3)));
            *(float4*)(ps + irow * PS_STRIDE + jh * 16 + 4 * q) = st;
        }
        const float* src = hb + (size_t)(jtp * 32 + hjr) * FOUT + hoc;
        #pragma unroll
        for (int m = 0; m < 8; m++) {
            float4 v = *(const float4*)(src + 32 * m);
            float4 st = make_float4(__uint_as_float(to_tf32(v.x)),
                                    __uint_as_float(to_tf32(v.y)),
                                    __uint_as_float(to_tf32(v.z)),
                                    __uint_as_float(to_tf32(v.w)));
            *(float4*)(hs + hjr * HS_STRIDE + hoc + 32 * m) = st;
        }
    };

    produce(0);

    for (int jt = 0; jt < 64; jt++) {
        __syncthreads();
        if (jt < 63) produce(jt + 1);

        const uint32_t* psu = (const uint32_t*)(smf + (jt & 1 ? SM_PS1 : SM_PS0));
        const uint32_t* hsu = (const uint32_t*)(smf + (jt & 1 ? SM_HS1 : SM_HS0));

        #pragma unroll
        for (int ks = 0; ks < 4; ks++) {
            uint32_t afr[4][4];
            #pragma unroll
            for (int ma = 0; ma < 4; ma++) {
                int base = (wi * 64 + ma * 16 + g) * PS_STRIDE + ks * 8 + tig;
                afr[ma][0] = psu[base];
                afr[ma][1] = psu[base + 8 * PS_STRIDE];
                afr[ma][2] = psu[base + 4];
                afr[ma][3] = psu[base + 8 * PS_STRIDE + 4];
            }
            uint32_t bfr[8][2];
            #pragma unroll
            for (int na = 0; na < 8; na++) {
                int o = wo * 64 + na * 8 + g;
                bfr[na][0] = hsu[(ks * 8 + tig) * HS_STRIDE + o];
                bfr[na][1] = hsu[(ks * 8 + tig + 4) * HS_STRIDE + o];
            }
            #pragma unroll
            for (int ma = 0; ma < 4; ma++)
                #pragma unroll
                for (int na = 0; na < 8; na++)
                    mma_tf32(acc[ma][na], afr[ma], bfr[na]);
        }
    }

    smf[SM_DSUM + jh * 128 + irow] = dloc;
    __syncthreads();

    #pragma unroll
    for (int ma = 0; ma < 4; ma++) {
        int ra = wi * 64 + ma * 16 + g;
        int rb = ra + 8;
        float da = smf[SM_DSUM + ra] + smf[SM_DSUM + 128 + ra];
        float db = smf[SM_DSUM + rb] + smf[SM_DSUM + 128 + rb];
        float inva = (da > 0.f) ? 1.f / da : 0.f;
        float invb = (db > 0.f) ? 1.f / db : 0.f;
        float* outa = out + ((size_t)b * NN + i0 + ra) * FOUT;
        float* outb = out + ((size_t)b * NN + i0 + rb) * FOUT;
        #pragma unroll
        for (int na = 0; na < 8; na++) {
            int col = wo * 64 + na * 8 + tig * 2;
            float v0 = acc[ma][na][0] * inva;
            float v1 = acc[ma][na][1] * inva;
            float v2 = acc[ma][na][2] * invb;
            float v3 = acc[ma][na][3] * invb;
            v0 = v0 > 0.f ? v0 : expm1f(v0);
            v1 = v1 > 0.f ? v1 : expm1f(v1);
            v2 = v2 > 0.f ? v2 : expm1f(v2);
            v3 = v3 > 0.f ? v3 : expm1f(v3);
            *(float2*)(outa + col) = make_float2(v0, v1);
            *(float2*)(outb + col) = make_float2(v2, v3);
        }
    }
}

// ---------------------------------------------------------------------------
extern "C" void kernel_launch(void* const* d_in, const int* in_sizes, int n_in,
                              void* d_out, int out_size)
{
    const float* x   = (const float*)d_in[0];
    const int*   adj = (const int*)d_in[1];
    const float* W   = (const float*)d_in[2];
    const float* a   = (const float*)d_in[3];
    float*       out = (float*)d_out;

    const int smem1 = (8320 + 8192) * 4;
    const int smem2 = ATTN_SMEM_FLOATS * 4;   // 112640 B
    cudaFuncSetAttribute(gemm_h_kernel, cudaFuncAttributeMaxDynamicSharedMemorySize, smem1);
    cudaFuncSetAttribute(attn_kernel,   cudaFuncAttributeMaxDynamicSharedMemorySize, smem2);

    gemm_h_kernel<<<128, 256, smem1>>>(x, W, a);
    attn_kernel<<<128, 256, smem2>>>(adj, out);
}

// round 4
// speedup vs baseline: 3.2016x; 1.3854x over previous
#include <cuda_runtime.h>
#include <math.h>
#include <stdint.h>

#define BB   8
#define NN   2048
#define FIN  512
#define FOUT 256

__device__ float g_h[(size_t)BB * NN * FOUT];   // 16.8 MB
__device__ float g_f[BB * NN];
__device__ float g_g[BB * NN];

__device__ __forceinline__ uint32_t to_tf32(float f) {
    uint32_t r; asm("cvt.rna.tf32.f32 %0, %1;" : "=r"(r) : "f"(f)); return r;
}
__device__ __forceinline__ void mma_tf32(float* d, const uint32_t* a, const uint32_t* b) {
    asm volatile(
        "mma.sync.aligned.m16n8k8.row.col.f32.tf32.tf32.f32 "
        "{%0,%1,%2,%3}, {%4,%5,%6,%7}, {%8,%9}, {%0,%1,%2,%3};"
        : "+f"(d[0]), "+f"(d[1]), "+f"(d[2]), "+f"(d[3])
        : "r"(a[0]), "r"(a[1]), "r"(a[2]), "r"(a[3]), "r"(b[0]), "r"(b[1]));
}
__device__ __forceinline__ uint32_t smem_u32(const void* p) {
    uint32_t a;
    asm("{ .reg .u64 t; cvta.to.shared.u64 t, %1; cvt.u32.u64 %0, t; }" : "=r"(a) : "l"(p));
    return a;
}
__device__ __forceinline__ void cp16(uint32_t dst, const void* src) {
    asm volatile("cp.async.cg.shared.global [%0], [%1], 16;" :: "r"(dst), "l"(src));
}
#define CP_COMMIT() asm volatile("cp.async.commit_group;" ::: "memory")
#define CP_WAIT0()  asm volatile("cp.async.wait_group 0;" ::: "memory")

// ===========================================================================
// Kernel 1: h = x @ W via split-tf32 mma (x=hi+lo, W=hi+lo, 3 MMAs) — fp32
// accuracy. Fused f = h@a1, g = h@a2 via shuffle+smem reduction.
// 128 blocks x 512 threads. Block tile 128(M) x 256(N), k-step 16, 32 steps.
// smem floats: xs[2][128*20] @0, ws[2][16*264] @5120.  (54272 B)
// ===========================================================================
#define XS_OFF 0
#define XS_SZ  2560
#define WS_OFF 5120
#define WS_SZ  4224
#define GH_SMEM 54272

__global__ __launch_bounds__(512, 1)
void gemm_h_kernel(const float* __restrict__ x, const float* __restrict__ W,
                   const float* __restrict__ a)
{
    extern __shared__ float sm[];
    const uint32_t sb = smem_u32(sm);

    const int t    = threadIdx.x;
    const int m0   = blockIdx.x * 128;
    const int warp = t >> 5, lane = t & 31;
    const int g    = lane >> 2, tig = lane & 3;
    const int wi   = warp >> 2, wo = warp & 3;

    // cp.async roles
    const int xrow = t >> 2, xseg = (t & 3) * 4;
    const int wrow = t >> 5, wseg = (t & 31) * 8;
    const float* xsrc = x + (size_t)(m0 + xrow) * FIN + xseg;
    const float* wsrc = W + (size_t)wrow * FOUT + wseg;

    auto issue = [&](int s) {
        uint32_t xd = sb + (XS_OFF + (s & 1) * XS_SZ + xrow * 20 + xseg) * 4;
        cp16(xd, xsrc + s * 16);
        uint32_t wd = sb + (WS_OFF + (s & 1) * WS_SZ + wrow * 264 + wseg) * 4;
        cp16(wd,      wsrc + (size_t)s * 16 * FOUT);
        cp16(wd + 16, wsrc + (size_t)s * 16 * FOUT + 4);
        CP_COMMIT();
    };

    float acc[2][8][4];
    #pragma unroll
    for (int ma = 0; ma < 2; ma++)
        #pragma unroll
        for (int na = 0; na < 8; na++)
            #pragma unroll
            for (int c = 0; c < 4; c++) acc[ma][na][c] = 0.f;

    issue(0);
    CP_WAIT0();
    __syncthreads();

    for (int s = 0; s < 32; s++) {
        if (s < 31) issue(s + 1);
        const float* xs = sm + XS_OFF + (s & 1) * XS_SZ;
        const float* ws = sm + WS_OFF + (s & 1) * WS_SZ;

        #pragma unroll
        for (int ks = 0; ks < 2; ks++) {
            uint32_t bhi[8][2], blo[8][2];
            #pragma unroll
            for (int na = 0; na < 8; na++) {
                int o = wo * 64 + na * 8 + g;
                float r0 = ws[(ks * 8 + tig) * 264 + o];
                float r1 = ws[(ks * 8 + tig + 4) * 264 + o];
                bhi[na][0] = to_tf32(r0);
                blo[na][0] = to_tf32(r0 - __uint_as_float(bhi[na][0]));
                bhi[na][1] = to_tf32(r1);
                blo[na][1] = to_tf32(r1 - __uint_as_float(bhi[na][1]));
            }
            #pragma unroll
            for (int ma = 0; ma < 2; ma++) {
                int R = wi * 32 + ma * 16;
                float r0 = xs[(R + g) * 20 + ks * 8 + tig];
                float r1 = xs[(R + g + 8) * 20 + ks * 8 + tig];
                float r2 = xs[(R + g) * 20 + ks * 8 + tig + 4];
                float r3 = xs[(R + g + 8) * 20 + ks * 8 + tig + 4];
                uint32_t ahi[4], alo[4];
                ahi[0] = to_tf32(r0); alo[0] = to_tf32(r0 - __uint_as_float(ahi[0]));
                ahi[1] = to_tf32(r1); alo[1] = to_tf32(r1 - __uint_as_float(ahi[1]));
                ahi[2] = to_tf32(r2); alo[2] = to_tf32(r2 - __uint_as_float(ahi[2]));
                ahi[3] = to_tf32(r3); alo[3] = to_tf32(r3 - __uint_as_float(ahi[3]));
                #pragma unroll
                for (int na = 0; na < 8; na++) {
                    mma_tf32(acc[ma][na], ahi, bhi[na]);
                    mma_tf32(acc[ma][na], alo, bhi[na]);
                    mma_tf32(acc[ma][na], ahi, blo[na]);
                }
            }
        }
        if (s < 31) CP_WAIT0();
        __syncthreads();
    }

    // ---- epilogue: write h, reduce f/g ----
    float a1c[16], a2c[16];
    #pragma unroll
    for (int na = 0; na < 8; na++) {
        int col = wo * 64 + na * 8 + tig * 2;
        a1c[2*na]   = __ldg(a + col);
        a1c[2*na+1] = __ldg(a + col + 1);
        a2c[2*na]   = __ldg(a + FOUT + col);
        a2c[2*na+1] = __ldg(a + FOUT + col + 1);
    }
    float* fred = sm;          // 512 floats
    float* gred = sm + 512;    // 512 floats

    #pragma unroll
    for (int ma = 0; ma < 2; ma++) {
        int ra = wi * 32 + ma * 16 + g;
        int rb = ra + 8;
        float fA = 0.f, gA = 0.f, fB = 0.f, gB = 0.f;
        #pragma unroll
        for (int na = 0; na < 8; na++) {
            int col = wo * 64 + na * 8 + tig * 2;
            float c0 = acc[ma][na][0], c1 = acc[ma][na][1];
            float c2 = acc[ma][na][2], c3 = acc[ma][na][3];
            *(float2*)(g_h + (size_t)(m0 + ra) * FOUT + col) = make_float2(c0, c1);
            *(float2*)(g_h + (size_t)(m0 + rb) * FOUT + col) = make_float2(c2, c3);
            fA += c0 * a1c[2*na] + c1 * a1c[2*na+1];
            gA += c0 * a2c[2*na] + c1 * a2c[2*na+1];
            fB += c2 * a1c[2*na] + c3 * a1c[2*na+1];
            gB += c2 * a2c[2*na] + c3 * a2c[2*na+1];
        }
        fA += __shfl_xor_sync(0xffffffffu, fA, 1); fA += __shfl_xor_sync(0xffffffffu, fA, 2);
        gA += __shfl_xor_sync(0xffffffffu, gA, 1); gA += __shfl_xor_sync(0xffffffffu, gA, 2);
        fB += __shfl_xor_sync(0xffffffffu, fB, 1); fB += __shfl_xor_sync(0xffffffffu, fB, 2);
        gB += __shfl_xor_sync(0xffffffffu, gB, 1); gB += __shfl_xor_sync(0xffffffffu, gB, 2);
        if (tig == 0) {
            fred[wo * 128 + ra] = fA; fred[wo * 128 + rb] = fB;
            gred[wo * 128 + ra] = gA; gred[wo * 128 + rb] = gB;
        }
    }
    __syncthreads();
    if (t < 128) {
        float fv = fred[t] + fred[128 + t] + fred[256 + t] + fred[384 + t];
        float gv = gred[t] + gred[128 + t] + gred[256 + t] + gred[384 + t];
        g_f[m0 + t] = fv;
        g_g[m0 + t] = gv;
    }
}

// ===========================================================================
// Kernel 2: attention, mma.sync tf32, pipelined:
//   - adj: 2-set register prefetch (loaded 2-3 iterations ahead)
//   - h tile: cp.async.cg into double-buffered smem (raw fp32, cvt at frag load)
//   - p tile: exp/mask computed from prefetched adj regs, STS as tf32
// 128 blocks x 256 threads, warp grid 2(i) x 4(o), warp tile 64x64.
// smem floats: dsum[256]@0 | gs[2048]@256 | ps[2][128*36]@2304 | hs[2][32*264]@11520
// ===========================================================================
#define AT_DSUM 0
#define AT_GS   256
#define AT_PS0  2304
#define AT_PS1  6912
#define AT_HS0  11520
#define AT_HS1  19968
#define AT_HS_SZ 8448
#define ATTN_SMEM (28416 * 4)

__global__ __launch_bounds__(256, 1)
void attn_kernel(const int* __restrict__ adj, float* __restrict__ out)
{
    extern __shared__ float smf[];
    const uint32_t sb = smem_u32(smf);

    const int t    = threadIdx.x;
    const int b    = blockIdx.x >> 4;
    const int i0   = (blockIdx.x & 15) << 7;
    const int warp = t >> 5, lane = t & 31;
    const int g    = lane >> 2, tig = lane & 3;
    const int wi   = warp >> 2, wo = warp & 3;

    // producer roles
    const int irow = t >> 1;        // 0..127
    const int jh   = t & 1;         // 16-j half
    const int hjr  = t >> 3;        // 0..31 (h row)
    const int hoc  = (t & 7) * 32;  // h col base (32 floats per thread)

    for (int j = t; j < NN; j += 256) smf[AT_GS + j] = g_g[b * NN + j];
    const float fv = g_f[b * NN + i0 + irow];
    const int*   adjrow = adj + ((size_t)b * NN + i0 + irow) * NN + jh * 16;
    const float* hb     = g_h + (size_t)b * NN * FOUT;

    float acc[4][8][4];
    #pragma unroll
    for (int ma = 0; ma < 4; ma++)
        #pragma unroll
        for (int na = 0; na < 8; na++)
            #pragma unroll
            for (int c = 0; c < 4; c++) acc[ma][na][c] = 0.f;
    float dloc = 0.f;

    auto cp_h = [&](int jt) {
        const float* src = hb + (size_t)(jt * 32 + hjr) * FOUT + hoc;
        uint32_t dst = sb + (AT_HS0 + (jt & 1) * AT_HS_SZ + hjr * 264 + hoc) * 4;
        #pragma unroll
        for (int q = 0; q < 8; q++) cp16(dst + q * 16, src + q * 4);
        CP_COMMIT();
    };
    auto ld_adj = [&](int jtp, int4* av) {
        #pragma unroll
        for (int q = 0; q < 4; q++) av[q] = *(const int4*)(adjrow + jtp * 32 + 4 * q);
    };
    auto store_p = [&](int jtp, const int4* av) {
        float* ps = smf + (jtp & 1 ? AT_PS1 : AT_PS0);
        const float* gsr = smf + AT_GS + jtp * 32 + jh * 16;
        #pragma unroll
        for (int q = 0; q < 4; q++) {
            int4 v = av[q];
            float z0 = fv + gsr[4*q+0]; z0 = z0 >= 0.f ? z0 : 0.2f * z0;
            float z1 = fv + gsr[4*q+1]; z1 = z1 >= 0.f ? z1 : 0.2f * z1;
            float z2 = fv + gsr[4*q+2]; z2 = z2 >= 0.f ? z2 : 0.2f * z2;
            float z3 = fv + gsr[4*q+3]; z3 = z3 >= 0.f ? z3 : 0.2f * z3;
            float p0 = (v.x > 0) ? __expf(z0) : 0.f;
            float p1 = (v.y > 0) ? __expf(z1) : 0.f;
            float p2 = (v.z > 0) ? __expf(z2) : 0.f;
            float p3 = (v.w > 0) ? __expf(z3) : 0.f;
            dloc += p0 + p1 + p2 + p3;
            float4 st = make_float4(__uint_as_float(to_tf32(p0)),
                                    __uint_as_float(to_tf32(p1)),
                                    __uint_as_float(to_tf32(p2)),
                                    __uint_as_float(to_tf32(p3)));
            *(float4*)(ps + irow * 36 + jh * 16 + 4 * q) = st;
        }
    };
    auto do_mma = [&](int jt) {
        const uint32_t* psu = (const uint32_t*)(smf + (jt & 1 ? AT_PS1 : AT_PS0));
        const float*    hsw = smf + (jt & 1 ? AT_HS1 : AT_HS0);
        #pragma unroll
        for (int ks = 0; ks < 4; ks++) {
            uint32_t afr[4][4];
            #pragma unroll
            for (int ma = 0; ma < 4; ma++) {
                int base = (wi * 64 + ma * 16 + g) * 36 + ks * 8 + tig;
                afr[ma][0] = psu[base];
                afr[ma][1] = psu[base + 8 * 36];
                afr[ma][2] = psu[base + 4];
                afr[ma][3] = psu[base + 8 * 36 + 4];
            }
            uint32_t bfr[8][2];
            #pragma unroll
            for (int na = 0; na < 8; na++) {
                int o = wo * 64 + na * 8 + g;
                bfr[na][0] = to_tf32(hsw[(ks * 8 + tig) * 264 + o]);
                bfr[na][1] = to_tf32(hsw[(ks * 8 + tig + 4) * 264 + o]);
            }
            #pragma unroll
            for (int ma = 0; ma < 4; ma++)
                #pragma unroll
                for (int na = 0; na < 8; na++)
                    mma_tf32(acc[ma][na], afr[ma], bfr[na]);
        }
    };

    // ---- prologue ----
    int4 A0[4], A1[4];
    cp_h(0);
    ld_adj(0, A0);
    ld_adj(1, A1);
    CP_WAIT0();
    __syncthreads();            // gs + h(0) visible
    store_p(0, A0);
    ld_adj(2, A0);
    __syncthreads();            // ps(0) visible

    // ---- main loop (unrolled x2 for register ping-pong) ----
    for (int jt = 0; jt < 64; jt += 2) {
        // even body: store from A1, reload A1
        {
            if (jt < 63) cp_h(jt + 1);
            do_mma(jt);
            if (jt < 63) store_p(jt + 1, A1);
            if (jt + 3 < 64) ld_adj(jt + 3, A1);
            if (jt < 63) CP_WAIT0();
            __syncthreads();
        }
        // odd body: store from A0, reload A0
        {
            int jo = jt + 1;
            if (jo < 63) cp_h(jo + 1);
            do_mma(jo);
            if (jo < 63) store_p(jo + 1, A0);
            if (jo + 3 < 64) ld_adj(jo + 3, A0);
            if (jo < 63) CP_WAIT0();
            __syncthreads();
        }
    }

    smf[AT_DSUM + jh * 128 + irow] = dloc;
    __syncthreads();

    #pragma unroll
    for (int ma = 0; ma < 4; ma++) {
        int ra = wi * 64 + ma * 16 + g;
        int rb = ra + 8;
        float da = smf[AT_DSUM + ra] + smf[AT_DSUM + 128 + ra];
        float db = smf[AT_DSUM + rb] + smf[AT_DSUM + 128 + rb];
        float inva = (da > 0.f) ? 1.f / da : 0.f;
        float invb = (db > 0.f) ? 1.f / db : 0.f;
        float* outa = out + ((size_t)b * NN + i0 + ra) * FOUT;
        float* outb = out + ((size_t)b * NN + i0 + rb) * FOUT;
        #pragma unroll
        for (int na = 0; na < 8; na++) {
            int col = wo * 64 + na * 8 + tig * 2;
            float v0 = acc[ma][na][0] * inva;
            float v1 = acc[ma][na][1] * inva;
            float v2 = acc[ma][na][2] * invb;
            float v3 = acc[ma][na][3] * invb;
            v0 = v0 > 0.f ? v0 : expm1f(v0);
            v1 = v1 > 0.f ? v1 : expm1f(v1);
            v2 = v2 > 0.f ? v2 : expm1f(v2);
            v3 = v3 > 0.f ? v3 : expm1f(v3);
            *(float2*)(outa + col) = make_float2(v0, v1);
            *(float2*)(outb + col) = make_float2(v2, v3);
        }
    }
}

// ---------------------------------------------------------------------------
extern "C" void kernel_launch(void* const* d_in, const int* in_sizes, int n_in,
                              void* d_out, int out_size)
{
    const float* x   = (const float*)d_in[0];
    const int*   adj = (const int*)d_in[1];
    const float* W   = (const float*)d_in[2];
    const float* a   = (const float*)d_in[3];
    float*       out = (float*)d_out;

    cudaFuncSetAttribute(gemm_h_kernel, cudaFuncAttributeMaxDynamicSharedMemorySize, GH_SMEM);
    cudaFuncSetAttribute(attn_kernel,   cudaFuncAttributeMaxDynamicSharedMemorySize, ATTN_SMEM);

    gemm_h_kernel<<<128, 512, GH_SMEM>>>(x, W, a);
    attn_kernel<<<128, 256, ATTN_SMEM>>>(adj, out);
}

// round 5
// speedup vs baseline: 3.3730x; 1.0535x over previous
#include <cuda_runtime.h>
#include <math.h>
#include <stdint.h>

#define BB   8
#define NN   2048
#define FIN  512
#define FOUT 256

__device__ float g_h[(size_t)BB * NN * FOUT];   // 16.8 MB
__device__ float g_f[BB * NN];
__device__ float g_g[BB * NN];

__device__ __forceinline__ uint32_t to_tf32(float f) {
    uint32_t r; asm("cvt.rna.tf32.f32 %0, %1;" : "=r"(r) : "f"(f)); return r;
}
__device__ __forceinline__ void mma_tf32(float* d, const uint32_t* a, const uint32_t* b) {
    asm volatile(
        "mma.sync.aligned.m16n8k8.row.col.f32.tf32.tf32.f32 "
        "{%0,%1,%2,%3}, {%4,%5,%6,%7}, {%8,%9}, {%0,%1,%2,%3};"
        : "+f"(d[0]), "+f"(d[1]), "+f"(d[2]), "+f"(d[3])
        : "r"(a[0]), "r"(a[1]), "r"(a[2]), "r"(a[3]), "r"(b[0]), "r"(b[1]));
}
__device__ __forceinline__ uint32_t smem_u32(const void* p) {
    uint32_t a;
    asm("{ .reg .u64 t; cvta.to.shared.u64 t, %1; cvt.u32.u64 %0, t; }" : "=r"(a) : "l"(p));
    return a;
}
__device__ __forceinline__ void cp16(uint32_t dst, const void* src) {
    asm volatile("cp.async.cg.shared.global [%0], [%1], 16;" :: "r"(dst), "l"(src));
}
#define CP_COMMIT() asm volatile("cp.async.commit_group;" ::: "memory")
#define CP_WAIT0()  asm volatile("cp.async.wait_group 0;" ::: "memory")

// ===========================================================================
// Kernel 1: h = x @ W via split-tf32 mma (3 MMAs) + fused f/g.  (R4, proven)
// 128 blocks x 512 threads.
// ===========================================================================
#define XS_OFF 0
#define XS_SZ  2560
#define WS_OFF 5120
#define WS_SZ  4224
#define GH_SMEM 54272

__global__ __launch_bounds__(512, 1)
void gemm_h_kernel(const float* __restrict__ x, const float* __restrict__ W,
                   const float* __restrict__ a)
{
    extern __shared__ float sm[];
    const uint32_t sb = smem_u32(sm);

    const int t    = threadIdx.x;
    const int m0   = blockIdx.x * 128;
    const int warp = t >> 5, lane = t & 31;
    const int g    = lane >> 2, tig = lane & 3;
    const int wi   = warp >> 2, wo = warp & 3;

    const int xrow = t >> 2, xseg = (t & 3) * 4;
    const int wrow = t >> 5, wseg = (t & 31) * 8;
    const float* xsrc = x + (size_t)(m0 + xrow) * FIN + xseg;
    const float* wsrc = W + (size_t)wrow * FOUT + wseg;

    auto issue = [&](int s) {
        uint32_t xd = sb + (XS_OFF + (s & 1) * XS_SZ + xrow * 20 + xseg) * 4;
        cp16(xd, xsrc + s * 16);
        uint32_t wd = sb + (WS_OFF + (s & 1) * WS_SZ + wrow * 264 + wseg) * 4;
        cp16(wd,      wsrc + (size_t)s * 16 * FOUT);
        cp16(wd + 16, wsrc + (size_t)s * 16 * FOUT + 4);
        CP_COMMIT();
    };

    float acc[2][8][4];
    #pragma unroll
    for (int ma = 0; ma < 2; ma++)
        #pragma unroll
        for (int na = 0; na < 8; na++)
            #pragma unroll
            for (int c = 0; c < 4; c++) acc[ma][na][c] = 0.f;

    issue(0);
    CP_WAIT0();
    __syncthreads();

    for (int s = 0; s < 32; s++) {
        if (s < 31) issue(s + 1);
        const float* xs = sm + XS_OFF + (s & 1) * XS_SZ;
        const float* ws = sm + WS_OFF + (s & 1) * WS_SZ;

        #pragma unroll
        for (int ks = 0; ks < 2; ks++) {
            uint32_t bhi[8][2], blo[8][2];
            #pragma unroll
            for (int na = 0; na < 8; na++) {
                int o = wo * 64 + na * 8 + g;
                float r0 = ws[(ks * 8 + tig) * 264 + o];
                float r1 = ws[(ks * 8 + tig + 4) * 264 + o];
                bhi[na][0] = to_tf32(r0);
                blo[na][0] = to_tf32(r0 - __uint_as_float(bhi[na][0]));
                bhi[na][1] = to_tf32(r1);
                blo[na][1] = to_tf32(r1 - __uint_as_float(bhi[na][1]));
            }
            #pragma unroll
            for (int ma = 0; ma < 2; ma++) {
                int R = wi * 32 + ma * 16;
                float r0 = xs[(R + g) * 20 + ks * 8 + tig];
                float r1 = xs[(R + g + 8) * 20 + ks * 8 + tig];
                float r2 = xs[(R + g) * 20 + ks * 8 + tig + 4];
                float r3 = xs[(R + g + 8) * 20 + ks * 8 + tig + 4];
                uint32_t ahi[4], alo[4];
                ahi[0] = to_tf32(r0); alo[0] = to_tf32(r0 - __uint_as_float(ahi[0]));
                ahi[1] = to_tf32(r1); alo[1] = to_tf32(r1 - __uint_as_float(ahi[1]));
                ahi[2] = to_tf32(r2); alo[2] = to_tf32(r2 - __uint_as_float(ahi[2]));
                ahi[3] = to_tf32(r3); alo[3] = to_tf32(r3 - __uint_as_float(ahi[3]));
                #pragma unroll
                for (int na = 0; na < 8; na++) {
                    mma_tf32(acc[ma][na], ahi, bhi[na]);
                    mma_tf32(acc[ma][na], alo, bhi[na]);
                    mma_tf32(acc[ma][na], ahi, blo[na]);
                }
            }
        }
        if (s < 31) CP_WAIT0();
        __syncthreads();
    }

    float a1c[16], a2c[16];
    #pragma unroll
    for (int na = 0; na < 8; na++) {
        int col = wo * 64 + na * 8 + tig * 2;
        a1c[2*na]   = __ldg(a + col);
        a1c[2*na+1] = __ldg(a + col + 1);
        a2c[2*na]   = __ldg(a + FOUT + col);
        a2c[2*na+1] = __ldg(a + FOUT + col + 1);
    }
    float* fred = sm;
    float* gred = sm + 512;

    #pragma unroll
    for (int ma = 0; ma < 2; ma++) {
        int ra = wi * 32 + ma * 16 + g;
        int rb = ra + 8;
        float fA = 0.f, gA = 0.f, fB = 0.f, gB = 0.f;
        #pragma unroll
        for (int na = 0; na < 8; na++) {
            int col = wo * 64 + na * 8 + tig * 2;
            float c0 = acc[ma][na][0], c1 = acc[ma][na][1];
            float c2 = acc[ma][na][2], c3 = acc[ma][na][3];
            *(float2*)(g_h + (size_t)(m0 + ra) * FOUT + col) = make_float2(c0, c1);
            *(float2*)(g_h + (size_t)(m0 + rb) * FOUT + col) = make_float2(c2, c3);
            fA += c0 * a1c[2*na] + c1 * a1c[2*na+1];
            gA += c0 * a2c[2*na] + c1 * a2c[2*na+1];
            fB += c2 * a1c[2*na] + c3 * a1c[2*na+1];
            gB += c2 * a2c[2*na] + c3 * a2c[2*na+1];
        }
        fA += __shfl_xor_sync(0xffffffffu, fA, 1); fA += __shfl_xor_sync(0xffffffffu, fA, 2);
        gA += __shfl_xor_sync(0xffffffffu, gA, 1); gA += __shfl_xor_sync(0xffffffffu, gA, 2);
        fB += __shfl_xor_sync(0xffffffffu, fB, 1); fB += __shfl_xor_sync(0xffffffffu, fB, 2);
        gB += __shfl_xor_sync(0xffffffffu, gB, 1); gB += __shfl_xor_sync(0xffffffffu, gB, 2);
        if (tig == 0) {
            fred[wo * 128 + ra] = fA; fred[wo * 128 + rb] = fB;
            gred[wo * 128 + ra] = gA; gred[wo * 128 + rb] = gB;
        }
    }
    __syncthreads();
    if (t < 128) {
        float fv = fred[t] + fred[128 + t] + fred[256 + t] + fred[384 + t];
        float gv = gred[t] + gred[128 + t] + gred[256 + t] + gred[384 + t];
        g_f[m0 + t] = fv;
        g_g[m0 + t] = gv;
    }
}

// ===========================================================================
// Kernel 2: attention, mma.sync tf32. NOW 512 threads: warp grid 4(i) x 4(o),
// warp tile 32x64, acc 64 regs/thread, 16 warps/SM (occ 25%).
// smem floats: dsum[512]@0 | gs[2048]@512 | ps[2][128*36]@2560 | hs[2][32*264]@11776
// ===========================================================================
#define AT_DSUM 0
#define AT_GS   512
#define AT_PS0  2560
#define AT_PS1  7168
#define AT_HS0  11776
#define AT_HS1  20224
#define AT_HS_SZ 8448
#define ATTN_SMEM (28672 * 4)

__global__ __launch_bounds__(512, 1)
void attn_kernel(const int* __restrict__ adj, float* __restrict__ out)
{
    extern __shared__ float smf[];
    const uint32_t sb = smem_u32(smf);

    const int t    = threadIdx.x;
    const int b    = blockIdx.x >> 4;
    const int i0   = (blockIdx.x & 15) << 7;
    const int warp = t >> 5, lane = t & 31;
    const int g    = lane >> 2, tig = lane & 3;
    const int wi   = warp >> 2, wo = warp & 3;

    // producer roles: 4 threads per p-row, 8 j each
    const int irow = t >> 2;        // 0..127
    const int jq   = t & 3;         // j-eighth (8 each)
    const int hjr  = t >> 4;        // 0..31 (h row)
    const int hoc  = (t & 15) * 16; // h col base (16 floats per thread)

    for (int j = t; j < NN; j += 512) smf[AT_GS + j] = g_g[b * NN + j];
    const float fv = g_f[b * NN + i0 + irow];
    const int*   adjrow = adj + ((size_t)b * NN + i0 + irow) * NN + jq * 8;
    const float* hb     = g_h + (size_t)b * NN * FOUT;

    float acc[2][8][4];
    #pragma unroll
    for (int ma = 0; ma < 2; ma++)
        #pragma unroll
        for (int na = 0; na < 8; na++)
            #pragma unroll
            for (int c = 0; c < 4; c++) acc[ma][na][c] = 0.f;
    float dloc = 0.f;

    auto cp_h = [&](int jt) {
        const float* src = hb + (size_t)(jt * 32 + hjr) * FOUT + hoc;
        uint32_t dst = sb + (AT_HS0 + (jt & 1) * AT_HS_SZ + hjr * 264 + hoc) * 4;
        #pragma unroll
        for (int q = 0; q < 4; q++) cp16(dst + q * 16, src + q * 4);
        CP_COMMIT();
    };
    auto ld_adj = [&](int jtp, int4* av) {
        av[0] = *(const int4*)(adjrow + jtp * 32);
        av[1] = *(const int4*)(adjrow + jtp * 32 + 4);
    };
    auto store_p = [&](int jtp, const int4* av) {
        float* ps = smf + (jtp & 1 ? AT_PS1 : AT_PS0);
        const float* gsr = smf + AT_GS + jtp * 32 + jq * 8;
        #pragma unroll
        for (int q = 0; q < 2; q++) {
            int4 v = av[q];
            float z0 = fv + gsr[4*q+0]; z0 = z0 >= 0.f ? z0 : 0.2f * z0;
            float z1 = fv + gsr[4*q+1]; z1 = z1 >= 0.f ? z1 : 0.2f * z1;
            float z2 = fv + gsr[4*q+2]; z2 = z2 >= 0.f ? z2 : 0.2f * z2;
            float z3 = fv + gsr[4*q+3]; z3 = z3 >= 0.f ? z3 : 0.2f * z3;
            float p0 = (v.x > 0) ? __expf(z0) : 0.f;
            float p1 = (v.y > 0) ? __expf(z1) : 0.f;
            float p2 = (v.z > 0) ? __expf(z2) : 0.f;
            float p3 = (v.w > 0) ? __expf(z3) : 0.f;
            dloc += p0 + p1 + p2 + p3;
            float4 st = make_float4(__uint_as_float(to_tf32(p0)),
                                    __uint_as_float(to_tf32(p1)),
                                    __uint_as_float(to_tf32(p2)),
                                    __uint_as_float(to_tf32(p3)));
            *(float4*)(ps + irow * 36 + jq * 8 + 4 * q) = st;
        }
    };
    auto do_mma = [&](int jt) {
        const uint32_t* psu = (const uint32_t*)(smf + (jt & 1 ? AT_PS1 : AT_PS0));
        const float*    hsw = smf + (jt & 1 ? AT_HS1 : AT_HS0);
        #pragma unroll
        for (int ks = 0; ks < 4; ks++) {
            uint32_t afr[2][4];
            #pragma unroll
            for (int ma = 0; ma < 2; ma++) {
                int base = (wi * 32 + ma * 16 + g) * 36 + ks * 8 + tig;
                afr[ma][0] = psu[base];
                afr[ma][1] = psu[base + 8 * 36];
                afr[ma][2] = psu[base + 4];
                afr[ma][3] = psu[base + 8 * 36 + 4];
            }
            uint32_t bfr[8][2];
            #pragma unroll
            for (int na = 0; na < 8; na++) {
                int o = wo * 64 + na * 8 + g;
                bfr[na][0] = to_tf32(hsw[(ks * 8 + tig) * 264 + o]);
                bfr[na][1] = to_tf32(hsw[(ks * 8 + tig + 4) * 264 + o]);
            }
            #pragma unroll
            for (int ma = 0; ma < 2; ma++)
                #pragma unroll
                for (int na = 0; na < 8; na++)
                    mma_tf32(acc[ma][na], afr[ma], bfr[na]);
        }
    };

    // ---- prologue ----
    int4 A0[2], A1[2];
    cp_h(0);
    ld_adj(0, A0);
    ld_adj(1, A1);
    CP_WAIT0();
    __syncthreads();
    store_p(0, A0);
    ld_adj(2, A0);
    __syncthreads();

    // ---- main loop (x2 unroll for adj register ping-pong) ----
    for (int jt = 0; jt < 64; jt += 2) {
        {
            if (jt < 63) cp_h(jt + 1);
            do_mma(jt);
            if (jt < 63) store_p(jt + 1, A1);
            if (jt + 3 < 64) ld_adj(jt + 3, A1);
            if (jt < 63) CP_WAIT0();
            __syncthreads();
        }
        {
            int jo = jt + 1;
            if (jo < 63) cp_h(jo + 1);
            do_mma(jo);
            if (jo < 63) store_p(jo + 1, A0);
            if (jo + 3 < 64) ld_adj(jo + 3, A0);
            if (jo < 63) CP_WAIT0();
            __syncthreads();
        }
    }

    smf[AT_DSUM + jq * 128 + irow] = dloc;
    __syncthreads();

    #pragma unroll
    for (int ma = 0; ma < 2; ma++) {
        int ra = wi * 32 + ma * 16 + g;
        int rb = ra + 8;
        float da = smf[AT_DSUM + ra] + smf[AT_DSUM + 128 + ra]
                 + smf[AT_DSUM + 256 + ra] + smf[AT_DSUM + 384 + ra];
        float db = smf[AT_DSUM + rb] + smf[AT_DSUM + 128 + rb]
                 + smf[AT_DSUM + 256 + rb] + smf[AT_DSUM + 384 + rb];
        float inva = (da > 0.f) ? 1.f / da : 0.f;
        float invb = (db > 0.f) ? 1.f / db : 0.f;
        float* outa = out + ((size_t)b * NN + i0 + ra) * FOUT;
        float* outb = out + ((size_t)b * NN + i0 + rb) * FOUT;
        #pragma unroll
        for (int na = 0; na < 8; na++) {
            int col = wo * 64 + na * 8 + tig * 2;
            float v0 = acc[ma][na][0] * inva;
            float v1 = acc[ma][na][1] * inva;
            float v2 = acc[ma][na][2] * invb;
            float v3 = acc[ma][na][3] * invb;
            v0 = v0 > 0.f ? v0 : expm1f(v0);
            v1 = v1 > 0.f ? v1 : expm1f(v1);
            v2 = v2 > 0.f ? v2 : expm1f(v2);
            v3 = v3 > 0.f ? v3 : expm1f(v3);
            *(float2*)(outa + col) = make_float2(v0, v1);
            *(float2*)(outb + col) = make_float2(v2, v3);
        }
    }
}

// ---------------------------------------------------------------------------
extern "C" void kernel_launch(void* const* d_in, const int* in_sizes, int n_in,
                              void* d_out, int out_size)
{
    const float* x   = (const float*)d_in[0];
    const int*   adj = (const int*)d_in[1];
    const float* W   = (const float*)d_in[2];
    const float* a   = (const float*)d_in[3];
    float*       out = (float*)d_out;

    cudaFuncSetAttribute(gemm_h_kernel, cudaFuncAttributeMaxDynamicSharedMemorySize, GH_SMEM);
    cudaFuncSetAttribute(attn_kernel,   cudaFuncAttributeMaxDynamicSharedMemorySize, ATTN_SMEM);

    gemm_h_kernel<<<128, 512, GH_SMEM>>>(x, W, a);
    attn_kernel<<<128, 512, ATTN_SMEM>>>(adj, out);
}

// round 8
// speedup vs baseline: 3.4504x; 1.0229x over previous
#include <cuda_runtime.h>
#include <math.h>
#include <stdint.h>

#define BB   8
#define NN   2048
#define FIN  512
#define FOUT 256

__device__ float g_h[(size_t)BB * NN * FOUT];   // tf32-prerounded h, 16.8 MB
__device__ float g_f[BB * NN];
__device__ float g_g[BB * NN];

__device__ __forceinline__ uint32_t to_tf32(float f) {
    uint32_t r; asm("cvt.rna.tf32.f32 %0, %1;" : "=r"(r) : "f"(f)); return r;
}
__device__ __forceinline__ void mma_tf32(float* d, const uint32_t* a, const uint32_t* b) {
    asm volatile(
        "mma.sync.aligned.m16n8k8.row.col.f32.tf32.tf32.f32 "
        "{%0,%1,%2,%3}, {%4,%5,%6,%7}, {%8,%9}, {%0,%1,%2,%3};"
        : "+f"(d[0]), "+f"(d[1]), "+f"(d[2]), "+f"(d[3])
        : "r"(a[0]), "r"(a[1]), "r"(a[2]), "r"(a[3]), "r"(b[0]), "r"(b[1]));
}
__device__ __forceinline__ uint32_t smem_u32(const void* p) {
    uint32_t a;
    asm("{ .reg .u64 t; cvta.to.shared.u64 t, %1; cvt.u32.u64 %0, t; }" : "=r"(a) : "l"(p));
    return a;
}
__device__ __forceinline__ void cp16(uint32_t dst, const void* src) {
    asm volatile("cp.async.cg.shared.global [%0], [%1], 16;" :: "r"(dst), "l"(src));
}
#define CP_COMMIT() asm volatile("cp.async.commit_group;" ::: "memory")
#define CP_WAIT0()  asm volatile("cp.async.wait_group 0;" ::: "memory")

// ===========================================================================
// Kernel 1: h = x @ W via split-tf32 mma (3 MMAs) + fused f/g.  (R4, proven)
// h stored PRE-ROUNDED to tf32 (f/g reduced from full fp32 accumulators).
// 128 blocks x 512 threads.
// ===========================================================================
#define XS_OFF 0
#define XS_SZ  2560
#define WS_OFF 5120
#define WS_SZ  4224
#define GH_SMEM 54272

__global__ __launch_bounds__(512, 1)
void gemm_h_kernel(const float* __restrict__ x, const float* __restrict__ W,
                   const float* __restrict__ a)
{
    extern __shared__ float sm[];
    const uint32_t sb = smem_u32(sm);

    const int t    = threadIdx.x;
    const int m0   = blockIdx.x * 128;
    const int warp = t >> 5, lane = t & 31;
    const int g    = lane >> 2, tig = lane & 3;
    const int wi   = warp >> 2, wo = warp & 3;

    const int xrow = t >> 2, xseg = (t & 3) * 4;
    const int wrow = t >> 5, wseg = (t & 31) * 8;
    const float* xsrc = x + (size_t)(m0 + xrow) * FIN + xseg;
    const float* wsrc = W + (size_t)wrow * FOUT + wseg;

    auto issue = [&](int s) {
        uint32_t xd = sb + (XS_OFF + (s & 1) * XS_SZ + xrow * 20 + xseg) * 4;
        cp16(xd, xsrc + s * 16);
        uint32_t wd = sb + (WS_OFF + (s & 1) * WS_SZ + wrow * 264 + wseg) * 4;
        cp16(wd,      wsrc + (size_t)s * 16 * FOUT);
        cp16(wd + 16, wsrc + (size_t)s * 16 * FOUT + 4);
        CP_COMMIT();
    };

    float acc[2][8][4];
    #pragma unroll
    for (int ma = 0; ma < 2; ma++)
        #pragma unroll
        for (int na = 0; na < 8; na++)
            #pragma unroll
            for (int c = 0; c < 4; c++) acc[ma][na][c] = 0.f;

    issue(0);
    CP_WAIT0();
    __syncthreads();

    for (int s = 0; s < 32; s++) {
        if (s < 31) issue(s + 1);
        const float* xs = sm + XS_OFF + (s & 1) * XS_SZ;
        const float* ws = sm + WS_OFF + (s & 1) * WS_SZ;

        #pragma unroll
        for (int ks = 0; ks < 2; ks++) {
            uint32_t bhi[8][2], blo[8][2];
            #pragma unroll
            for (int na = 0; na < 8; na++) {
                int o = wo * 64 + na * 8 + g;
                float r0 = ws[(ks * 8 + tig) * 264 + o];
                float r1 = ws[(ks * 8 + tig + 4) * 264 + o];
                bhi[na][0] = to_tf32(r0);
                blo[na][0] = to_tf32(r0 - __uint_as_float(bhi[na][0]));
                bhi[na][1] = to_tf32(r1);
                blo[na][1] = to_tf32(r1 - __uint_as_float(bhi[na][1]));
            }
            #pragma unroll
            for (int ma = 0; ma < 2; ma++) {
                int R = wi * 32 + ma * 16;
                float r0 = xs[(R + g) * 20 + ks * 8 + tig];
                float r1 = xs[(R + g + 8) * 20 + ks * 8 + tig];
                float r2 = xs[(R + g) * 20 + ks * 8 + tig + 4];
                float r3 = xs[(R + g + 8) * 20 + ks * 8 + tig + 4];
                uint32_t ahi[4], alo[4];
                ahi[0] = to_tf32(r0); alo[0] = to_tf32(r0 - __uint_as_float(ahi[0]));
                ahi[1] = to_tf32(r1); alo[1] = to_tf32(r1 - __uint_as_float(ahi[1]));
                ahi[2] = to_tf32(r2); alo[2] = to_tf32(r2 - __uint_as_float(ahi[2]));
                ahi[3] = to_tf32(r3); alo[3] = to_tf32(r3 - __uint_as_float(ahi[3]));
                #pragma unroll
                for (int na = 0; na < 8; na++) {
                    mma_tf32(acc[ma][na], ahi, bhi[na]);
                    mma_tf32(acc[ma][na], alo, bhi[na]);
                    mma_tf32(acc[ma][na], ahi, blo[na]);
                }
            }
        }
        if (s < 31) CP_WAIT0();
        __syncthreads();
    }

    float a1c[16], a2c[16];
    #pragma unroll
    for (int na = 0; na < 8; na++) {
        int col = wo * 64 + na * 8 + tig * 2;
        a1c[2*na]   = __ldg(a + col);
        a1c[2*na+1] = __ldg(a + col + 1);
        a2c[2*na]   = __ldg(a + FOUT + col);
        a2c[2*na+1] = __ldg(a + FOUT + col + 1);
    }
    float* fred = sm;
    float* gred = sm + 512;

    #pragma unroll
    for (int ma = 0; ma < 2; ma++) {
        int ra = wi * 32 + ma * 16 + g;
        int rb = ra + 8;
        float fA = 0.f, gA = 0.f, fB = 0.f, gB = 0.f;
        #pragma unroll
        for (int na = 0; na < 8; na++) {
            int col = wo * 64 + na * 8 + tig * 2;
            float c0 = acc[ma][na][0], c1 = acc[ma][na][1];
            float c2 = acc[ma][na][2], c3 = acc[ma][na][3];
            // store h pre-rounded to tf32 (what attn's MMA would consume anyway)
            float2 sA = make_float2(__uint_as_float(to_tf32(c0)), __uint_as_float(to_tf32(c1)));
            float2 sB = make_float2(__uint_as_float(to_tf32(c2)), __uint_as_float(to_tf32(c3)));
            *(float2*)(g_h + (size_t)(m0 + ra) * FOUT + col) = sA;
            *(float2*)(g_h + (size_t)(m0 + rb) * FOUT + col) = sB;
            fA += c0 * a1c[2*na] + c1 * a1c[2*na+1];
            gA += c0 * a2c[2*na] + c1 * a2c[2*na+1];
            fB += c2 * a1c[2*na] + c3 * a1c[2*na+1];
            gB += c2 * a2c[2*na] + c3 * a2c[2*na+1];
        }
        fA += __shfl_xor_sync(0xffffffffu, fA, 1); fA += __shfl_xor_sync(0xffffffffu, fA, 2);
        gA += __shfl_xor_sync(0xffffffffu, gA, 1); gA += __shfl_xor_sync(0xffffffffu, gA, 2);
        fB += __shfl_xor_sync(0xffffffffu, fB, 1); fB += __shfl_xor_sync(0xffffffffu, fB, 2);
        gB += __shfl_xor_sync(0xffffffffu, gB, 1); gB += __shfl_xor_sync(0xffffffffu, gB, 2);
        if (tig == 0) {
            fred[wo * 128 + ra] = fA; fred[wo * 128 + rb] = fB;
            gred[wo * 128 + ra] = gA; gred[wo * 128 + rb] = gB;
        }
    }
    __syncthreads();
    if (t < 128) {
        float fv = fred[t] + fred[128 + t] + fred[256 + t] + fred[384 + t];
        float gv = gred[t] + gred[128 + t] + gred[256 + t] + gred[384 + t];
        g_f[m0 + t] = fv;
        g_g[m0 + t] = gv;
    }
}

// ===========================================================================
// Kernel 2: attention, mma.sync tf32. 1024 threads: warp grid 8(i) x 4(o),
// warp tile 16x64, acc 32 regs/thread, 32 warps/SM (occ 50%).
// h in g_h already tf32-rounded -> B frags load with NO cvt.
// smem floats: dsum[1024]@0 | gs[2048]@1024 | ps[2][128*36]@3072 | hs[2][32*264]@12288
// ===========================================================================
#define AT_DSUM 0
#define AT_GS   1024
#define AT_PS0  3072
#define AT_PS1  7680
#define AT_HS0  12288
#define AT_HS1  20736
#define AT_HS_SZ 8448
#define ATTN_SMEM (29184 * 4)

__global__ __launch_bounds__(1024, 1)
void attn_kernel(const int* __restrict__ adj, float* __restrict__ out)
{
    extern __shared__ float smf[];
    const uint32_t sb = smem_u32(smf);

    const int t    = threadIdx.x;
    const int b    = blockIdx.x >> 4;
    const int i0   = (blockIdx.x & 15) << 7;
    const int warp = t >> 5, lane = t & 31;
    const int g    = lane >> 2, tig = lane & 3;
    const int wiq  = warp >> 2, wo = warp & 3;   // wiq 0..7, wo 0..3

    // producer roles: 8 threads per p-row, 4 j each
    const int irow = t >> 3;        // 0..127
    const int jq   = t & 7;         // j-eighth of 32 (4 each)
    const int hjr  = t >> 5;        // 0..31 (h row)
    const int hoc  = (t & 31) * 8;  // h col base (8 floats = 2 cp16)

    for (int j = t; j < NN; j += 1024) smf[AT_GS + j] = g_g[b * NN + j];
    const float fv = g_f[b * NN + i0 + irow];
    const int*   adjrow = adj + ((size_t)b * NN + i0 + irow) * NN + jq * 4;
    const float* hb     = g_h + (size_t)b * NN * FOUT;

    float acc[8][4];
    #pragma unroll
    for (int na = 0; na < 8; na++)
        #pragma unroll
        for (int c = 0; c < 4; c++) acc[na][c] = 0.f;
    float dloc = 0.f;

    auto cp_h = [&](int jt) {
        const float* src = hb + (size_t)(jt * 32 + hjr) * FOUT + hoc;
        uint32_t dst = sb + (AT_HS0 + (jt & 1) * AT_HS_SZ + hjr * 264 + hoc) * 4;
        cp16(dst,      src);
        cp16(dst + 16, src + 4);
        CP_COMMIT();
    };
    auto ld_adj = [&](int jtp, int4& av) {
        av = *(const int4*)(adjrow + jtp * 32);
    };
    auto store_p = [&](int jtp, const int4& v) {
        float* ps = smf + (jtp & 1 ? AT_PS1 : AT_PS0);
        const float* gsr = smf + AT_GS + jtp * 32 + jq * 4;
        float z0 = fv + gsr[0]; z0 = z0 >= 0.f ? z0 : 0.2f * z0;
        float z1 = fv + gsr[1]; z1 = z1 >= 0.f ? z1 : 0.2f * z1;
        float z2 = fv + gsr[2]; z2 = z2 >= 0.f ? z2 : 0.2f * z2;
        float z3 = fv + gsr[3]; z3 = z3 >= 0.f ? z3 : 0.2f * z3;
        float p0 = (v.x > 0) ? __expf(z0) : 0.f;
        float p1 = (v.y > 0) ? __expf(z1) : 0.f;
        float p2 = (v.z > 0) ? __expf(z2) : 0.f;
        float p3 = (v.w > 0) ? __expf(z3) : 0.f;
        dloc += p0 + p1 + p2 + p3;
        float4 st = make_float4(__uint_as_float(to_tf32(p0)),
                                __uint_as_float(to_tf32(p1)),
                                __uint_as_float(to_tf32(p2)),
                                __uint_as_float(to_tf32(p3)));
        *(float4*)(ps + irow * 36 + jq * 4) = st;
    };
    auto do_mma = [&](int jt) {
        const uint32_t* psu = (const uint32_t*)(smf + (jt & 1 ? AT_PS1 : AT_PS0));
        const uint32_t* hsu = (const uint32_t*)(smf + (jt & 1 ? AT_HS1 : AT_HS0));
        #pragma unroll
        for (int ks = 0; ks < 4; ks++) {
            uint32_t afr[4];
            {
                int base = (wiq * 16 + g) * 36 + ks * 8 + tig;
                afr[0] = psu[base];
                afr[1] = psu[base + 8 * 36];
                afr[2] = psu[base + 4];
                afr[3] = psu[base + 8 * 36 + 4];
            }
            uint32_t bfr[8][2];
            #pragma unroll
            for (int na = 0; na < 8; na++) {
                int o = wo * 64 + na * 8 + g;
                bfr[na][0] = hsu[(ks * 8 + tig) * 264 + o];
                bfr[na][1] = hsu[(ks * 8 + tig + 4) * 264 + o];
            }
            #pragma unroll
            for (int na = 0; na < 8; na++)
                mma_tf32(acc[na], afr, bfr[na]);
        }
    };

    // ---- prologue ----
    int4 A0, A1;
    cp_h(0);
    ld_adj(0, A0);
    ld_adj(1, A1);
    CP_WAIT0();
    __syncthreads();
    store_p(0, A0);
    ld_adj(2, A0);
    __syncthreads();

    // ---- main loop (x2 unroll for adj register ping-pong) ----
    for (int jt = 0; jt < 64; jt += 2) {
        {
            if (jt < 63) cp_h(jt + 1);
            do_mma(jt);
            if (jt < 63) store_p(jt + 1, A1);
            if (jt + 3 < 64) ld_adj(jt + 3, A1);
            if (jt < 63) CP_WAIT0();
            __syncthreads();
        }
        {
            int jo = jt + 1;
            if (jo < 63) cp_h(jo + 1);
            do_mma(jo);
            if (jo < 63) store_p(jo + 1, A0);
            if (jo + 3 < 64) ld_adj(jo + 3, A0);
            if (jo < 63) CP_WAIT0();
            __syncthreads();
        }
    }

    smf[AT_DSUM + jq * 128 + irow] = dloc;
    __syncthreads();

    {
        int ra = wiq * 16 + g;
        int rb = ra + 8;
        float da = 0.f, db = 0.f;
        #pragma unroll
        for (int s = 0; s < 8; s++) {
            da += smf[AT_DSUM + s * 128 + ra];
            db += smf[AT_DSUM + s * 128 + rb];
        }
        float inva = (da > 0.f) ? 1.f / da : 0.f;
        float invb = (db > 0.f) ? 1.f / db : 0.f;
        float* outa = out + ((size_t)b * NN + i0 + ra) * FOUT;
        float* outb = out + ((size_t)b * NN + i0 + rb) * FOUT;
        #pragma unroll
        for (int na = 0; na < 8; na++) {
            int col = wo * 64 + na * 8 + tig * 2;
            float v0 = acc[na][0] * inva;
            float v1 = acc[na][1] * inva;
            float v2 = acc[na][2] * invb;
            float v3 = acc[na][3] * invb;
            v0 = v0 > 0.f ? v0 : expm1f(v0);
            v1 = v1 > 0.f ? v1 : expm1f(v1);
            v2 = v2 > 0.f ? v2 : expm1f(v2);
            v3 = v3 > 0.f ? v3 : expm1f(v3);
            *(float2*)(outa + col) = make_float2(v0, v1);
            *(float2*)(outb + col) = make_float2(v2, v3);
        }
    }
}

// ---------------------------------------------------------------------------
extern "C" void kernel_launch(void* const* d_in, const int* in_sizes, int n_in,
                              void* d_out, int out_size)
{
    const float* x   = (const float*)d_in[0];
    const int*   adj = (const int*)d_in[1];
    const float* W   = (const float*)d_in[2];
    const float* a   = (const float*)d_in[3];
    float*       out = (float*)d_out;

    cudaFuncSetAttribute(gemm_h_kernel, cudaFuncAttributeMaxDynamicSharedMemorySize, GH_SMEM);
    cudaFuncSetAttribute(attn_kernel,   cudaFuncAttributeMaxDynamicSharedMemorySize, ATTN_SMEM);

    gemm_h_kernel<<<128, 512, GH_SMEM>>>(x, W, a);
    attn_kernel<<<128, 1024, ATTN_SMEM>>>(adj, out);
}